// round 2
// baseline (speedup 1.0000x reference)
#include <cuda_runtime.h>

#define W 960
#define H 512
#define C 16
#define HW (H * W)

// HWC scratch image: [H*W][16] floats = 31.5 MB (static device array — no alloc)
__device__ float g_hwc[HW * C];

// ---------------- transpose CHW -> HWC ----------------
#define TP_PIX 128
__global__ __launch_bounds__(256) void transpose_kernel(const float* __restrict__ img)
{
    __shared__ float tile[TP_PIX][C + 1];
    const int pix0 = blockIdx.x * TP_PIX;

    // load: coalesced reads from each channel plane
#pragma unroll
    for (int i = threadIdx.x; i < TP_PIX * C; i += 256) {
        const int c = i / TP_PIX;
        const int p = i % TP_PIX;
        tile[p][c] = img[c * HW + pix0 + p];
    }
    __syncthreads();

    // store: fully coalesced HWC writes
#pragma unroll
    for (int i = threadIdx.x; i < TP_PIX * C; i += 256) {
        const int p = i / C;
        const int c = i % C;
        g_hwc[(pix0 + p) * C + c] = tile[p][c];
    }
}

// ---------------- fused reconstruct ----------------
// thread = (pixel, 4-channel group). blockIdx.z = channel group (0..3).
__global__ __launch_bounds__(256) void recon_kernel(
    const float* __restrict__ offx,  // [H,W]
    const float* __restrict__ offy,  // [H,W]
    float* __restrict__ out)         // [C,H,W]
{
    const int w = blockIdx.x * 32 + (threadIdx.x & 31);
    const int h = blockIdx.y * 8 + (threadIdx.x >> 5);
    const int cg = blockIdx.z;           // 4-channel group
    const float4* __restrict__ hwc4 = (const float4*)g_hwc;  // [HW][4] of float4

    const float fw = (float)w;
    const float fh = (float)h;

    float4 acc = make_float4(0.f, 0.f, 0.f, 0.f);

#pragma unroll
    for (int di = 0; di < 3; di++) {
        int hh = h + di - 1;
        hh = (hh < 0) ? -hh : ((hh >= H) ? (2 * H - 2 - hh) : hh);
#pragma unroll
        for (int dj = 0; dj < 3; dj++) {
            int ww = w + dj - 1;
            ww = (ww < 0) ? -ww : ((ww >= W) ? (2 * W - 2 - ww) : ww);
            const int oidx = hh * W + ww;
            const float sx = __ldg(offx + oidx);
            const float sy = __ldg(offy + oidx);

            // replicate reference arithmetic exactly
            float cx = fminf(fmaxf(fw - sx, 0.0f), (float)(W - 1));
            float cy = fminf(fmaxf(fh - sy, 0.0f), (float)(H - 1));
            float gx = (cx - (float)(W / 2)) / (float)(W / 2);
            float gy = (cy - (float)(H / 2)) / (float)(H / 2);
            float ix = (gx + 1.0f) * 0.5f * (float)(W - 1);
            float iy = (gy + 1.0f) * 0.5f * (float)(H - 1);

            float x0f = floorf(ix);
            float y0f = floorf(iy);
            float wx1 = ix - x0f;
            float wy1 = iy - y0f;
            float wx0 = 1.0f - wx1;
            float wy0 = 1.0f - wy1;

            const float w00 = wx0 * wy0;
            const float w10 = wx1 * wy0;
            const float w01 = wx0 * wy1;
            const float w11 = wx1 * wy1;

            // float4 index: pixel*(16 floats/4) + cg
            const int b = ((int)y0f * W + (int)x0f) * 4 + cg;

            const float4 v00 = __ldg(hwc4 + b);
            const float4 v10 = __ldg(hwc4 + b + 4);
            const float4 v01 = __ldg(hwc4 + b + W * 4);
            const float4 v11 = __ldg(hwc4 + b + W * 4 + 4);

            acc.x += v00.x * w00 + v10.x * w10 + v01.x * w01 + v11.x * w11;
            acc.y += v00.y * w00 + v10.y * w10 + v01.y * w01 + v11.y * w11;
            acc.z += v00.z * w00 + v10.z * w10 + v01.z * w01 + v11.z * w11;
            acc.w += v00.w * w00 + v10.w * w10 + v01.w * w01 + v11.w * w11;
        }
    }

    const int pix = h * W + w;
    const float inv9 = 1.0f / 9.0f;
    const int c0 = cg * 4;
    out[(c0 + 0) * HW + pix] = acc.x * inv9;
    out[(c0 + 1) * HW + pix] = acc.y * inv9;
    out[(c0 + 2) * HW + pix] = acc.z * inv9;
    out[(c0 + 3) * HW + pix] = acc.w * inv9;
}

extern "C" void kernel_launch(void* const* d_in, const int* in_sizes, int n_in,
                              void* d_out, int out_size)
{
    const float* img  = (const float*)d_in[0];  // right_input [1,16,512,960]
    const float* offx = (const float*)d_in[1];  // offset_x    [1,1,512,960]
    const float* offy = (const float*)d_in[2];  // offset_y    [1,1,512,960]
    float* out = (float*)d_out;                 // [1,16,512,960]

    transpose_kernel<<<HW / TP_PIX, 256>>>(img);

    dim3 block(256);
    dim3 grid(W / 32, H / 8, 4);  // 30 x 64 x 4 channel-groups
    recon_kernel<<<grid, block>>>(offx, offy, out);
}

// round 3
// speedup vs baseline: 1.5778x; 1.5778x over previous
#include <cuda_runtime.h>

#define W 960
#define H 512
#define C 16
#define HW (H * W)

// HWC scratch image: [H*W][16] floats (static device array — no alloc)
__device__ float g_hwc[HW * C];

// ---------------- transpose CHW -> HWC ----------------
#define TP_PIX 128
__global__ __launch_bounds__(256) void transpose_kernel(const float* __restrict__ img)
{
    __shared__ float tile[TP_PIX][C + 1];
    const int pix0 = blockIdx.x * TP_PIX;
#pragma unroll
    for (int i = threadIdx.x; i < TP_PIX * C; i += 256) {
        const int c = i / TP_PIX, p = i % TP_PIX;
        tile[p][c] = img[c * HW + pix0 + p];
    }
    __syncthreads();
#pragma unroll
    for (int i = threadIdx.x; i < TP_PIX * C; i += 256) {
        const int p = i / C, c = i % C;
        g_hwc[(pix0 + p) * C + c] = tile[p][c];
    }
}

// ---------------- scatter-patch reconstruct ----------------
#define TILE 16
#define HALO 18
#define NUNIT (HALO * HALO)   /* 324 offset pixels per block */
#define NWAVE 6               /* 6 * 64 units >= 324 */
#define ACC_PITCH 265         /* odd pitch (mod 8 != 0 in float4 units) -> fewer bank conflicts */

__global__ __launch_bounds__(256) void recon_scatter(
    const float* __restrict__ offx,
    const float* __restrict__ offy,
    float* __restrict__ out)
{
    __shared__ float4 acc[4][ACC_PITCH];   // [cg][cell 16x16 + pad]

    const int tid = threadIdx.x;
    const int cg  = tid & 3;               // channel group = lane%4
    const int h0  = blockIdx.y * TILE;
    const int w0  = blockIdx.x * TILE;
    const float4* __restrict__ imgp = (const float4*)g_hwc;

    // zero accumulator
    for (int i = tid; i < 4 * ACC_PITCH; i += 256)
        ((float4*)acc)[i] = make_float4(0.f, 0.f, 0.f, 0.f);
    __syncthreads();

    for (int wave = 0; wave < NWAVE; wave++) {
        const int u = wave * 64 + (tid >> 2);
        int hh = 0, ww = 0;
        bool valid = false;
        if (u < NUNIT) {
            hh = h0 - 1 + u / HALO;
            ww = w0 - 1 + u % HALO;
            valid = (hh >= 0) && (hh < H) && (ww >= 0) && (ww < W);
        }

        float4 o[9];
        int cells[9];
#pragma unroll
        for (int p = 0; p < 9; p++) { o[p] = make_float4(0.f,0.f,0.f,0.f); cells[p] = -1; }

        if (valid) {
            const float sx = __ldg(offx + hh * W + ww);
            const float sy = __ldg(offy + hh * W + ww);

            // ---- x weight vectors (4 wide, 2 nonzero, multiplicity folded) ----
            float wx[3][4];
            int px;
            {
                int x0a[3]; float fxa[3], ma[3];
                int pmin = W;
#pragma unroll
                for (int dj = 0; dj < 3; dj++) {
                    const int wt = ww + 1 - dj;
                    float m = (wt >= 0 && wt < W) ? 1.f : 0.f;
                    if (ww == 1     && wt == 0    ) m += 1.f;   // reflection doubling
                    if (ww == W - 2 && wt == W - 1) m += 1.f;
                    float cx  = fminf(fmaxf((float)wt - sx, 0.f), (float)(W - 1));
                    float ix  = cx * ((float)(W - 1) / (float)W);
                    float x0f = floorf(ix);
                    x0a[dj] = (int)x0f; fxa[dj] = ix - x0f; ma[dj] = m;
                    if (m != 0.f) pmin = min(pmin, x0a[dj]);
                }
                px = min(pmin, W - 4);
#pragma unroll
                for (int dj = 0; dj < 3; dj++) {
                    const int l = x0a[dj] - px;
#pragma unroll
                    for (int c = 0; c < 4; c++)
                        wx[dj][c] = ma[dj] * ((c == l) ? (1.f - fxa[dj])
                                            : ((c == l + 1) ? fxa[dj] : 0.f));
                }
            }

            // ---- y weight vectors ----
            float wy[3][4];
            int py;
            {
                int y0a[3]; float fya[3], ma[3];
                int pmin = H;
#pragma unroll
                for (int di = 0; di < 3; di++) {
                    const int ht = hh + 1 - di;
                    float m = (ht >= 0 && ht < H) ? 1.f : 0.f;
                    if (hh == 1     && ht == 0    ) m += 1.f;
                    if (hh == H - 2 && ht == H - 1) m += 1.f;
                    float cy  = fminf(fmaxf((float)ht - sy, 0.f), (float)(H - 1));
                    float iy  = cy * ((float)(H - 1) / (float)H);
                    float y0f = floorf(iy);
                    y0a[di] = (int)y0f; fya[di] = iy - y0f; ma[di] = m;
                    if (m != 0.f) pmin = min(pmin, y0a[di]);
                }
                py = min(pmin, H - 4);
#pragma unroll
                for (int di = 0; di < 3; di++) {
                    const int l = y0a[di] - py;
#pragma unroll
                    for (int r = 0; r < 4; r++)
                        wy[di][r] = ma[di] * ((r == l) ? (1.f - fya[di])
                                            : ((r == l + 1) ? fya[di] : 0.f));
                }
            }

            // ---- 4x4 patch, row-streamed; lanes cg=0..3 load 64B contiguous ----
            const int base = (py * W + px) * 4 + cg;
#pragma unroll
            for (int r = 0; r < 4; r++) {
                const int rb = base + r * (W * 4);
                const float4 P0 = __ldg(imgp + rb);
                const float4 P1 = __ldg(imgp + rb + 4);
                const float4 P2 = __ldg(imgp + rb + 8);
                const float4 P3 = __ldg(imgp + rb + 12);
#pragma unroll
                for (int dj = 0; dj < 3; dj++) {
                    float4 t;
                    t.x = P0.x*wx[dj][0] + P1.x*wx[dj][1] + P2.x*wx[dj][2] + P3.x*wx[dj][3];
                    t.y = P0.y*wx[dj][0] + P1.y*wx[dj][1] + P2.y*wx[dj][2] + P3.y*wx[dj][3];
                    t.z = P0.z*wx[dj][0] + P1.z*wx[dj][1] + P2.z*wx[dj][2] + P3.z*wx[dj][3];
                    t.w = P0.w*wx[dj][0] + P1.w*wx[dj][1] + P2.w*wx[dj][2] + P3.w*wx[dj][3];
#pragma unroll
                    for (int di = 0; di < 3; di++) {
                        const float g = wy[di][r];
                        o[di*3+dj].x += t.x * g;
                        o[di*3+dj].y += t.y * g;
                        o[di*3+dj].z += t.z * g;
                        o[di*3+dj].w += t.w * g;
                    }
                }
            }

            // ---- target cells ----
#pragma unroll
            for (int di = 0; di < 3; di++) {
                const int lh = (hh + 1 - di) - h0;
#pragma unroll
                for (int dj = 0; dj < 3; dj++) {
                    const int lw = (ww + 1 - dj) - w0;
                    cells[di*3+dj] = (lh >= 0 && lh < TILE && lw >= 0 && lw < TILE)
                                   ? (lh * TILE + lw) : -1;
                }
            }
        }

        // ---- 9 race-free phases: per phase, thread->cell is injective ----
#pragma unroll
        for (int p = 0; p < 9; p++) {
            if (cells[p] >= 0) {
                float4 a = acc[cg][cells[p]];
                a.x += o[p].x; a.y += o[p].y; a.z += o[p].z; a.w += o[p].w;
                acc[cg][cells[p]] = a;
            }
            __syncthreads();
        }
    }

    // ---- writeback: thread = cell, 16 channels, coalesced per channel plane ----
    const int ph = tid >> 4, pw = tid & 15;
    const int gidx = (h0 + ph) * W + (w0 + pw);
    const float inv9 = 1.0f / 9.0f;
#pragma unroll
    for (int k = 0; k < 4; k++) {
        const float4 a = acc[k][tid];
        out[(4*k + 0) * HW + gidx] = a.x * inv9;
        out[(4*k + 1) * HW + gidx] = a.y * inv9;
        out[(4*k + 2) * HW + gidx] = a.z * inv9;
        out[(4*k + 3) * HW + gidx] = a.w * inv9;
    }
}

extern "C" void kernel_launch(void* const* d_in, const int* in_sizes, int n_in,
                              void* d_out, int out_size)
{
    const float* img  = (const float*)d_in[0];  // right_input [1,16,512,960]
    const float* offx = (const float*)d_in[1];  // offset_x    [1,1,512,960]
    const float* offy = (const float*)d_in[2];  // offset_y    [1,1,512,960]
    float* out = (float*)d_out;                 // [1,16,512,960]

    transpose_kernel<<<HW / TP_PIX, 256>>>(img);

    dim3 grid(W / TILE, H / TILE);              // 60 x 32
    recon_scatter<<<grid, 256>>>(offx, offy, out);
}

// round 4
// speedup vs baseline: 1.7615x; 1.1165x over previous
#include <cuda_runtime.h>

#define W 960
#define H 512
#define C 16
#define HW (H * W)

// HWC scratch image: [H*W][16] floats (static device array — no alloc)
__device__ float g_hwc[HW * C];

// ---------------- transpose CHW -> HWC ----------------
#define TP_PIX 128
__global__ __launch_bounds__(256) void transpose_kernel(const float* __restrict__ img)
{
    __shared__ float tile[TP_PIX][C + 1];
    const int pix0 = blockIdx.x * TP_PIX;
#pragma unroll
    for (int i = threadIdx.x; i < TP_PIX * C; i += 256) {
        const int c = i / TP_PIX, p = i % TP_PIX;
        tile[p][c] = img[c * HW + pix0 + p];
    }
    __syncthreads();
#pragma unroll
    for (int i = threadIdx.x; i < TP_PIX * C; i += 256) {
        const int p = i / C, c = i % C;
        g_hwc[(pix0 + p) * C + c] = tile[p][c];
    }
}

// ---------------- scatter-patch reconstruct ----------------
#define TILE 16
#define HALO 18
#define NUNIT (HALO * HALO)   /* 324 */
#define NWAVE 6               /* 6 * 64 >= 324 */
#define ACC_PITCH 257         /* odd float4 pitch -> cg groups hit distinct banks */

__global__ __launch_bounds__(256, 3) void recon_scatter(
    const float* __restrict__ offx,
    const float* __restrict__ offy,
    float* __restrict__ out)
{
    __shared__ float4 acc[4][ACC_PITCH];   // [cg][cell]
    __shared__ float4 up[NUNIT][5];        // per-unit params

    const int tid = threadIdx.x;
    const int h0 = blockIdx.y * TILE;
    const int w0 = blockIdx.x * TILE;
    const float4* __restrict__ imgp = (const float4*)g_hwc;

    // zero accumulator
    for (int i = tid; i < 4 * ACC_PITCH; i += 256)
        ((float4*)acc)[i] = make_float4(0.f, 0.f, 0.f, 0.f);

    // ---------- phase A: per-unit params, computed ONCE ----------
    for (int u = tid; u < NUNIT; u += 256) {
        const int ur = u / HALO, uc = u % HALO;
        const int hh = h0 - 1 + ur, ww = w0 - 1 + uc;
        float4 z = make_float4(0.f, 0.f, 0.f, 0.f);
        float4 wxv[3] = {z, z, z};
        float4 wy01 = z, misc = z;

        if (hh >= 0 && hh < H && ww >= 0 && ww < W) {
            const float sx = __ldg(offx + hh * W + ww);
            const float sy = __ldg(offy + hh * W + ww);

            // ---- x: dense 4-wide weight vectors ----
            int x0a[3]; float fxa[3], ma[3]; int pmin = W;
#pragma unroll
            for (int dj = 0; dj < 3; dj++) {
                const int wt = ww + 1 - dj;
                float m = (wt >= 0 && wt < W) ? 1.f : 0.f;
                if (ww == 1     && wt == 0    ) m += 1.f;   // reflection doubling
                if (ww == W - 2 && wt == W - 1) m += 1.f;
                float cx  = fminf(fmaxf((float)wt - sx, 0.f), (float)(W - 1));
                float ix  = cx * ((float)(W - 1) / (float)W);
                float x0f = floorf(ix);
                x0a[dj] = (int)x0f; fxa[dj] = ix - x0f; ma[dj] = m;
                if (m != 0.f) pmin = min(pmin, x0a[dj]);
            }
            const int px = min(pmin, W - 4);
#pragma unroll
            for (int dj = 0; dj < 3; dj++) {
                const int l = x0a[dj] - px;
                float v[4];
#pragma unroll
                for (int c = 0; c < 4; c++)
                    v[c] = ma[dj] * ((c == l) ? (1.f - fxa[dj])
                                   : ((c == l + 1) ? fxa[dj] : 0.f));
                wxv[dj] = make_float4(v[0], v[1], v[2], v[3]);
            }

            // ---- y: 2 scalar weights + row index per di ----
            int y0a[3]; float fya[3], mya[3]; int qmin = H;
#pragma unroll
            for (int di = 0; di < 3; di++) {
                const int ht = hh + 1 - di;
                float m = (ht >= 0 && ht < H) ? 1.f : 0.f;
                if (hh == 1     && ht == 0    ) m += 1.f;
                if (hh == H - 2 && ht == H - 1) m += 1.f;
                float cy  = fminf(fmaxf((float)ht - sy, 0.f), (float)(H - 1));
                float iy  = cy * ((float)(H - 1) / (float)H);
                float y0f = floorf(iy);
                y0a[di] = (int)y0f; fya[di] = iy - y0f; mya[di] = m;
                if (m != 0.f) qmin = min(qmin, y0a[di]);
            }
            const int py = min(qmin, H - 4);
            int lpack = 0;
            float av[3], bv[3];
#pragma unroll
            for (int di = 0; di < 3; di++) {
                int l = y0a[di] - py;
                l = min(max(l, 0), 2);
                av[di] = mya[di] * (1.f - fya[di]);
                bv[di] = mya[di] * fya[di];
                lpack |= l << (4 * di);
            }
            wy01 = make_float4(av[0], bv[0], av[1], bv[1]);
            misc = make_float4(av[2], bv[2], __int_as_float(lpack),
                               __int_as_float((py * W + px) * 4));
        }
        up[u][0] = wxv[0]; up[u][1] = wxv[1]; up[u][2] = wxv[2];
        up[u][3] = wy01;   up[u][4] = misc;
    }
    __syncthreads();

    // ---------- phase B: per-di streamed sampling + race-free scatter ----------
    const int cg = tid & 3;

    for (int wave = 0; wave < NWAVE; wave++) {
        const int u = wave * 64 + (tid >> 2);
        const bool has = (u < NUNIT);
        const int uu = has ? u : 0;

        const float4 wxv0 = up[uu][0];
        const float4 wxv1 = up[uu][1];
        const float4 wxv2 = up[uu][2];
        const float4 wy01 = up[uu][3];
        const float4 misc = up[uu][4];
        const int lpack = __float_as_int(misc.z);
        const int base  = __float_as_int(misc.w) + cg;
        const int ur = uu / HALO, uc = uu % HALO;

#pragma unroll
        for (int di = 0; di < 3; di++) {
            const float a = (di == 0) ? wy01.x : (di == 1) ? wy01.z : misc.x;
            const float b = (di == 0) ? wy01.y : (di == 1) ? wy01.w : misc.y;
            const int l  = (lpack >> (4 * di)) & 0xF;
            const int rb = base + l * (W * 4);

            float4 o[3];
            {   // row l
                const float4 P0 = __ldg(imgp + rb);
                const float4 P1 = __ldg(imgp + rb + 4);
                const float4 P2 = __ldg(imgp + rb + 8);
                const float4 P3 = __ldg(imgp + rb + 12);
#pragma unroll
                for (int dj = 0; dj < 3; dj++) {
                    const float4 wd = (dj == 0) ? wxv0 : (dj == 1) ? wxv1 : wxv2;
                    float4 t;
                    t.x = P0.x*wd.x + P1.x*wd.y + P2.x*wd.z + P3.x*wd.w;
                    t.y = P0.y*wd.x + P1.y*wd.y + P2.y*wd.z + P3.y*wd.w;
                    t.z = P0.z*wd.x + P1.z*wd.y + P2.z*wd.z + P3.z*wd.w;
                    t.w = P0.w*wd.x + P1.w*wd.y + P2.w*wd.z + P3.w*wd.w;
                    o[dj].x = t.x * a; o[dj].y = t.y * a;
                    o[dj].z = t.z * a; o[dj].w = t.w * a;
                }
            }
            {   // row l+1
                const int rb1 = rb + W * 4;
                const float4 P0 = __ldg(imgp + rb1);
                const float4 P1 = __ldg(imgp + rb1 + 4);
                const float4 P2 = __ldg(imgp + rb1 + 8);
                const float4 P3 = __ldg(imgp + rb1 + 12);
#pragma unroll
                for (int dj = 0; dj < 3; dj++) {
                    const float4 wd = (dj == 0) ? wxv0 : (dj == 1) ? wxv1 : wxv2;
                    float4 t;
                    t.x = P0.x*wd.x + P1.x*wd.y + P2.x*wd.z + P3.x*wd.w;
                    t.y = P0.y*wd.x + P1.y*wd.y + P2.y*wd.z + P3.y*wd.w;
                    t.z = P0.z*wd.x + P1.z*wd.y + P2.z*wd.z + P3.z*wd.w;
                    t.w = P0.w*wd.x + P1.w*wd.y + P2.w*wd.z + P3.w*wd.w;
                    o[dj].x += t.x * b; o[dj].y += t.y * b;
                    o[dj].z += t.z * b; o[dj].w += t.w * b;
                }
            }

            const int row = ur - di;
#pragma unroll
            for (int dj = 0; dj < 3; dj++) {
                const int col = uc - dj;
                const bool wr = has && ((unsigned)row < (unsigned)TILE)
                                    && ((unsigned)col < (unsigned)TILE);
                if (wr) {
                    const int idx = row * TILE + col;
                    float4 v = acc[cg][idx];
                    v.x += o[dj].x; v.y += o[dj].y;
                    v.z += o[dj].z; v.w += o[dj].w;
                    acc[cg][idx] = v;
                }
                __syncthreads();
            }
        }
    }

    // ---------- writeback ----------
    const int ph = tid >> 4, pw = tid & 15;
    const int gidx = (h0 + ph) * W + (w0 + pw);
    const float inv9 = 1.0f / 9.0f;
#pragma unroll
    for (int k = 0; k < 4; k++) {
        const float4 a = acc[k][tid];
        out[(4*k + 0) * HW + gidx] = a.x * inv9;
        out[(4*k + 1) * HW + gidx] = a.y * inv9;
        out[(4*k + 2) * HW + gidx] = a.z * inv9;
        out[(4*k + 3) * HW + gidx] = a.w * inv9;
    }
}

extern "C" void kernel_launch(void* const* d_in, const int* in_sizes, int n_in,
                              void* d_out, int out_size)
{
    const float* img  = (const float*)d_in[0];  // right_input [1,16,512,960]
    const float* offx = (const float*)d_in[1];  // offset_x    [1,1,512,960]
    const float* offy = (const float*)d_in[2];  // offset_y    [1,1,512,960]
    float* out = (float*)d_out;                 // [1,16,512,960]

    transpose_kernel<<<HW / TP_PIX, 256>>>(img);

    dim3 grid(W / TILE, H / TILE);              // 60 x 32
    recon_scatter<<<grid, 256>>>(offx, offy, out);
}

// round 5
// speedup vs baseline: 1.9306x; 1.0960x over previous
#include <cuda_runtime.h>

#define W 960
#define H 512
#define C 16
#define HW (H * W)

// HWC scratch image: [H*W][16] floats (static device array — no alloc)
__device__ float g_hwc[HW * C];

// ---------------- transpose CHW -> HWC (vectorized) ----------------
#define TP_PIX 64
__global__ __launch_bounds__(256) void transpose_kernel(const float* __restrict__ img)
{
    __shared__ float tile[TP_PIX][C + 1];
    const int pix0 = blockIdx.x * TP_PIX;

    // load: 16 channels x 16 float4 (=64 pixels) coalesced
    {
        const int c = threadIdx.x >> 4;          // 0..15
        const int v = threadIdx.x & 15;          // 0..15 float4 within row
        const float4 d = *(const float4*)(img + c * HW + pix0 + v * 4);
        tile[v * 4 + 0][c] = d.x;
        tile[v * 4 + 1][c] = d.y;
        tile[v * 4 + 2][c] = d.z;
        tile[v * 4 + 3][c] = d.w;
    }
    __syncthreads();

    // store: 64 pixels x 4 cg float4, fully coalesced
    {
        const int p  = threadIdx.x >> 2;         // 0..63
        const int cg = threadIdx.x & 3;          // 0..3
        float4 d;
        d.x = tile[p][cg * 4 + 0];
        d.y = tile[p][cg * 4 + 1];
        d.z = tile[p][cg * 4 + 2];
        d.w = tile[p][cg * 4 + 3];
        ((float4*)g_hwc)[(pix0 + p) * 4 + cg] = d;
    }
}

// ---------------- scatter-patch reconstruct ----------------
#define TILE 16
#define HALO 18
#define NUNIT (HALO * HALO)   /* 324 */
#define NWAVE 6               /* 6 * 64 >= 324 */
#define ACC_PITCH 257

__global__ __launch_bounds__(256, 2) void recon_scatter(
    const float* __restrict__ offx,
    const float* __restrict__ offy,
    float* __restrict__ out)
{
    __shared__ float4 acc[4][ACC_PITCH];   // [cg][cell]
    __shared__ float4 up[NUNIT][7];        // wx0,wx1,wx2, wy0,wy1,wy2, misc

    const int tid = threadIdx.x;
    const int h0 = blockIdx.y * TILE;
    const int w0 = blockIdx.x * TILE;
    const float4* __restrict__ imgp = (const float4*)g_hwc;

    for (int i = tid; i < 4 * ACC_PITCH; i += 256)
        ((float4*)acc)[i] = make_float4(0.f, 0.f, 0.f, 0.f);

    // ---------- phase A: per-unit params, computed ONCE ----------
    for (int u = tid; u < NUNIT; u += 256) {
        const int ur = u / HALO, uc = u % HALO;
        const int hh = h0 - 1 + ur, ww = w0 - 1 + uc;
        const float4 z = make_float4(0.f, 0.f, 0.f, 0.f);
        float4 wxv[3] = {z, z, z};
        float4 wyv[3] = {z, z, z};
        float4 misc = z;

        if (hh >= 0 && hh < H && ww >= 0 && ww < W) {
            const float sx = __ldg(offx + hh * W + ww);
            const float sy = __ldg(offy + hh * W + ww);

            // ---- x: dense 4-wide weight vectors ----
            int x0a[3]; float fxa[3], ma[3]; int pmin = W;
#pragma unroll
            for (int dj = 0; dj < 3; dj++) {
                const int wt = ww + 1 - dj;
                float m = (wt >= 0 && wt < W) ? 1.f : 0.f;
                if (ww == 1     && wt == 0    ) m += 1.f;   // reflection doubling
                if (ww == W - 2 && wt == W - 1) m += 1.f;
                float cx  = fminf(fmaxf((float)wt - sx, 0.f), (float)(W - 1));
                float ix  = cx * ((float)(W - 1) / (float)W);
                float x0f = floorf(ix);
                x0a[dj] = (int)x0f; fxa[dj] = ix - x0f; ma[dj] = m;
                if (m != 0.f) pmin = min(pmin, x0a[dj]);
            }
            const int px = min(pmin, W - 4);
#pragma unroll
            for (int dj = 0; dj < 3; dj++) {
                const int l = x0a[dj] - px;
                float v[4];
#pragma unroll
                for (int c = 0; c < 4; c++)
                    v[c] = ma[dj] * ((c == l) ? (1.f - fxa[dj])
                                   : ((c == l + 1) ? fxa[dj] : 0.f));
                wxv[dj] = make_float4(v[0], v[1], v[2], v[3]);
            }

            // ---- y: dense 4-wide weight vectors over patch rows ----
            int y0a[3]; float fya[3], mya[3]; int qmin = H;
#pragma unroll
            for (int di = 0; di < 3; di++) {
                const int ht = hh + 1 - di;
                float m = (ht >= 0 && ht < H) ? 1.f : 0.f;
                if (hh == 1     && ht == 0    ) m += 1.f;
                if (hh == H - 2 && ht == H - 1) m += 1.f;
                float cy  = fminf(fmaxf((float)ht - sy, 0.f), (float)(H - 1));
                float iy  = cy * ((float)(H - 1) / (float)H);
                float y0f = floorf(iy);
                y0a[di] = (int)y0f; fya[di] = iy - y0f; mya[di] = m;
                if (m != 0.f) qmin = min(qmin, y0a[di]);
            }
            const int py = min(qmin, H - 4);
#pragma unroll
            for (int di = 0; di < 3; di++) {
                const int l = y0a[di] - py;   // always in [0,2]
                float v[4];
#pragma unroll
                for (int r = 0; r < 4; r++)
                    v[r] = mya[di] * ((r == l) ? (1.f - fya[di])
                                    : ((r == l + 1) ? fya[di] : 0.f));
                wyv[di] = make_float4(v[0], v[1], v[2], v[3]);
            }
            misc.x = __int_as_float((py * W + px) * 4);
            misc.y = 1.0f;   // has-work flag
        }
        up[u][0] = wxv[0]; up[u][1] = wxv[1]; up[u][2] = wxv[2];
        up[u][3] = wyv[0]; up[u][4] = wyv[1]; up[u][5] = wyv[2];
        up[u][6] = misc;
    }
    __syncthreads();

    // ---------- phase B: single-pass 4-row patch stream ----------
    const int cg = tid & 3;

    for (int wave = 0; wave < NWAVE; wave++) {
        const int u = wave * 64 + (tid >> 2);
        const bool has = (u < NUNIT);
        const int uu = has ? u : 0;

        const float4 wx0 = up[uu][0];
        const float4 wx1 = up[uu][1];
        const float4 wx2 = up[uu][2];
        const float4 wy0 = up[uu][3];
        const float4 wy1 = up[uu][4];
        const float4 wy2 = up[uu][5];
        const float4 misc = up[uu][6];
        const int base = __float_as_int(misc.x) + cg;
        const int ur = uu / HALO, uc = uu % HALO;

        const float4 z = make_float4(0.f, 0.f, 0.f, 0.f);
        float4 o[9] = {z, z, z, z, z, z, z, z, z};

#pragma unroll
        for (int r = 0; r < 4; r++) {
            const int rb = base + r * (W * 4);
            const float4 P0 = __ldg(imgp + rb);
            const float4 P1 = __ldg(imgp + rb + 4);
            const float4 P2 = __ldg(imgp + rb + 8);
            const float4 P3 = __ldg(imgp + rb + 12);
#pragma unroll
            for (int dj = 0; dj < 3; dj++) {
                const float4 wd = (dj == 0) ? wx0 : (dj == 1) ? wx1 : wx2;
                float4 t;
                t.x = P0.x*wd.x + P1.x*wd.y + P2.x*wd.z + P3.x*wd.w;
                t.y = P0.y*wd.x + P1.y*wd.y + P2.y*wd.z + P3.y*wd.w;
                t.z = P0.z*wd.x + P1.z*wd.y + P2.z*wd.z + P3.z*wd.w;
                t.w = P0.w*wd.x + P1.w*wd.y + P2.w*wd.z + P3.w*wd.w;
#pragma unroll
                for (int di = 0; di < 3; di++) {
                    const float4 wv = (di == 0) ? wy0 : (di == 1) ? wy1 : wy2;
                    const float g = (r == 0) ? wv.x : (r == 1) ? wv.y
                                  : (r == 2) ? wv.z : wv.w;
                    o[di*3+dj].x += t.x * g;
                    o[di*3+dj].y += t.y * g;
                    o[di*3+dj].z += t.z * g;
                    o[di*3+dj].w += t.w * g;
                }
            }
        }

        // ---- 9 race-free scatter phases ----
#pragma unroll
        for (int di = 0; di < 3; di++) {
            const int row = ur - di;
#pragma unroll
            for (int dj = 0; dj < 3; dj++) {
                const int col = uc - dj;
                const bool wr = has && ((unsigned)row < (unsigned)TILE)
                                    && ((unsigned)col < (unsigned)TILE);
                if (wr) {
                    const int idx = row * TILE + col;
                    float4 v = acc[cg][idx];
                    v.x += o[di*3+dj].x; v.y += o[di*3+dj].y;
                    v.z += o[di*3+dj].z; v.w += o[di*3+dj].w;
                    acc[cg][idx] = v;
                }
                __syncthreads();
            }
        }
    }

    // ---------- writeback ----------
    const int ph = tid >> 4, pw = tid & 15;
    const int gidx = (h0 + ph) * W + (w0 + pw);
    const float inv9 = 1.0f / 9.0f;
#pragma unroll
    for (int k = 0; k < 4; k++) {
        const float4 a = acc[k][tid];
        out[(4*k + 0) * HW + gidx] = a.x * inv9;
        out[(4*k + 1) * HW + gidx] = a.y * inv9;
        out[(4*k + 2) * HW + gidx] = a.z * inv9;
        out[(4*k + 3) * HW + gidx] = a.w * inv9;
    }
}

extern "C" void kernel_launch(void* const* d_in, const int* in_sizes, int n_in,
                              void* d_out, int out_size)
{
    const float* img  = (const float*)d_in[0];  // right_input [1,16,512,960]
    const float* offx = (const float*)d_in[1];  // offset_x    [1,1,512,960]
    const float* offy = (const float*)d_in[2];  // offset_y    [1,1,512,960]
    float* out = (float*)d_out;                 // [1,16,512,960]

    transpose_kernel<<<HW / TP_PIX, 256>>>(img);

    dim3 grid(W / TILE, H / TILE);              // 60 x 32
    recon_scatter<<<grid, 256>>>(offx, offy, out);
}